// round 1
// baseline (speedup 1.0000x reference)
#include <cuda_runtime.h>
#include <cstdint>

using ull = unsigned long long;

static constexpr int NN    = 16384;  // points per batch
static constexpr int KK    = 16;     // neighbors
static constexpr int CC    = 64;     // feature channels
static constexpr int DD    = 64;     // mlp out channels
static constexpr int WARPS = 8;      // warps per block
static constexpr float SLOPE = 0.1f;

// ---- packed f32x2 helpers (Blackwell FFMA2 path) ----
__device__ __forceinline__ ull pfma(ull a, ull b, ull c) {
    ull d; asm("fma.rn.f32x2 %0, %1, %2, %3;" : "=l"(d) : "l"(a), "l"(b), "l"(c)); return d;
}
__device__ __forceinline__ ull padd(ull a, ull b) {
    ull d; asm("add.rn.f32x2 %0, %1, %2;" : "=l"(d) : "l"(a), "l"(b)); return d;
}
__device__ __forceinline__ ull pmul(ull a, ull b) {
    ull d; asm("mul.rn.f32x2 %0, %1, %2;" : "=l"(d) : "l"(a), "l"(b)); return d;
}
__device__ __forceinline__ ull dup2(float x) {
    unsigned u = __float_as_uint(x);
    ull r; asm("mov.b64 %0, {%1, %1};" : "=l"(r) : "r"(u)); return r;
}
__device__ __forceinline__ ull pk2(float lo, float hi) {
    ull r; asm("mov.b64 %0, {%1, %2};" : "=l"(r)
               : "r"(__float_as_uint(lo)), "r"(__float_as_uint(hi))); return r;
}

__global__ __launch_bounds__(WARPS * 32)
void lfa_kernel(const float* __restrict__ features,
                const float* __restrict__ geom,
                const float* __restrict__ w,
                const float* __restrict__ bias,
                const long long* __restrict__ nidx,
                float* __restrict__ out,
                int npts)
{
    __shared__ alignas(16) ull sg[WARPS][KK][4];   // geom, each float duplicated to f32x2
    __shared__ int  si[WARPS][KK];                 // neighbor rows
    __shared__ ull  sw[4][32];                     // w packed: (w[d][f], w[d+32][f])
    __shared__ ull  sb[32];                        // bias packed
    __shared__ int  sIs64;

    const int tid  = threadIdx.x;
    const int lane = tid & 31;
    const int wid  = tid >> 5;

    // ---- block-wide init: packed weights/bias + index dtype detection ----
    if (tid < 128) {
        int f = tid >> 5, d = tid & 31;
        sw[f][d] = pk2(w[d * 4 + f], w[(d + 32) * 4 + f]);
    }
    if (tid < 32) sb[tid] = pk2(bias[tid], bias[tid + 32]);
    if (tid == 0) sIs64 = 1;
    __syncthreads();
    // If data is really int32, an int64 read packs two indices -> >= 2^32 w.h.p.
    if (tid < KK) {
        long long v = nidx[tid];
        if (v < 0 || v >= (long long)NN) atomicAnd(&sIs64, 0);
    }
    __syncthreads();
    const int is64 = sIs64;

    const ull w0 = sw[0][lane], w1 = sw[1][lane], w2 = sw[2][lane], w3 = sw[3][lane];
    const ull b2 = sb[lane];

    const int point = blockIdx.x * WARPS + wid;
    if (point >= npts) return;
    const int bb = point / NN;

    // ---- per-warp staging: geom (duplicated pairs) + neighbor indices ----
    if (lane < KK) {
        const float4* gp = reinterpret_cast<const float4*>(geom + (size_t)point * (KK * 4));
        float4 g = gp[lane];
        sg[wid][lane][0] = dup2(g.x);
        sg[wid][lane][1] = dup2(g.y);
        sg[wid][lane][2] = dup2(g.z);
        sg[wid][lane][3] = dup2(g.w);
        long long v;
        if (is64) v = nidx[(size_t)point * KK + lane];
        else      v = (long long)reinterpret_cast<const int*>(nidx)[(size_t)point * KK + lane];
        si[wid][lane] = (int)v;
    }
    __syncwarp();

    // ---- issue all gather loads first (lane owns channels 2*lane, 2*lane+1) ----
    const float* fb = features + (size_t)bb * NN * CC + 2 * lane;
    ull vv[KK];
#pragma unroll
    for (int k = 0; k < KK; k++) {
        int row = si[wid][k];
        vv[k] = *reinterpret_cast<const ull*>(fb + (size_t)row * CC);
    }

    // ---- geom MLP: lane owns outputs (lane, lane+32) as one f32x2 ----
    // lrelu(x) = 0.55*x + 0.45*|x|  (slope 0.1)  =>
    // mean_k lrelu = c1*sum(x) + c2*sum(|x|)
    ull xsum = 0ULL, xabs = 0ULL;
#pragma unroll
    for (int k = 0; k < KK; k++) {
        const ulonglong2* p = reinterpret_cast<const ulonglong2*>(&sg[wid][k][0]);
        ulonglong2 ga = p[0];
        ulonglong2 gb = p[1];
        ull x = b2;
        x = pfma(ga.x, w0, x);
        x = pfma(ga.y, w1, x);
        x = pfma(gb.x, w2, x);
        x = pfma(gb.y, w3, x);
        xsum = padd(xsum, x);
        xabs = padd(xabs, x & 0x7FFFFFFF7FFFFFFFULL);  // |x| on both halves (ALU pipe)
    }

    const float c1 = (1.0f + SLOPE) * 0.5f / (float)KK;
    const float c2 = (1.0f - SLOPE) * 0.5f / (float)KK;
    const ull t = pfma(xsum, dup2(c1), pmul(xabs, dup2(c2)));

    // ---- gather mean ----
    ull gsum = 0ULL;
#pragma unroll
    for (int k = 0; k < KK; k++) gsum = padd(gsum, vv[k]);
    gsum = pmul(gsum, dup2(1.0f / (float)KK));

    // ---- store: out[point] = [t_mean (64) | f_mean (64)] ----
    float* op = out + (size_t)point * (DD + CC);
    op[lane]      = __uint_as_float((unsigned)t);
    op[lane + 32] = __uint_as_float((unsigned)(t >> 32));
    *reinterpret_cast<ull*>(op + DD + 2 * lane) = gsum;
}

extern "C" void kernel_launch(void* const* d_in, const int* in_sizes, int n_in,
                              void* d_out, int out_size)
{
    const float*     features = (const float*)d_in[0];
    const float*     geom     = (const float*)d_in[1];
    const float*     w        = (const float*)d_in[2];
    const float*     b        = (const float*)d_in[3];
    const long long* nidx     = (const long long*)d_in[4];

    const int npts   = in_sizes[4] / KK;            // B*N
    const int blocks = (npts + WARPS - 1) / WARPS;

    lfa_kernel<<<blocks, WARPS * 32>>>(features, geom, w, b, nidx, (float*)d_out, npts);
}

// round 2
// speedup vs baseline: 1.1024x; 1.1024x over previous
#include <cuda_runtime.h>
#include <cstdint>

using ull  = unsigned long long;
using uint = unsigned int;

static constexpr int NN    = 16384;  // points per batch
static constexpr int KK    = 16;     // neighbors
static constexpr int CC    = 64;     // feature channels
static constexpr int DD    = 64;     // mlp out channels
static constexpr int WARPS = 8;      // warps per block
static constexpr int PPW   = 8;      // target points per warp (amortize setup)
static constexpr float SLOPE = 0.1f;

#define FULLM 0xFFFFFFFFu
static constexpr ull ABSM = 0x7FFFFFFF7FFFFFFFULL;

// ---- packed f32x2 helpers (Blackwell FFMA2 path) ----
__device__ __forceinline__ ull pfma(ull a, ull b, ull c) {
    ull d; asm("fma.rn.f32x2 %0, %1, %2, %3;" : "=l"(d) : "l"(a), "l"(b), "l"(c)); return d;
}
__device__ __forceinline__ ull padd(ull a, ull b) {
    ull d; asm("add.rn.f32x2 %0, %1, %2;" : "=l"(d) : "l"(a), "l"(b)); return d;
}
__device__ __forceinline__ ull pmul(ull a, ull b) {
    ull d; asm("mul.rn.f32x2 %0, %1, %2;" : "=l"(d) : "l"(a), "l"(b)); return d;
}
__device__ __forceinline__ ull dup2(float x) {
    unsigned u = __float_as_uint(x);
    ull r; asm("mov.b64 %0, {%1, %1};" : "=l"(r) : "r"(u)); return r;
}
__device__ __forceinline__ ull pk2(float lo, float hi) {
    ull r; asm("mov.b64 %0, {%1, %2};" : "=l"(r)
               : "r"(__float_as_uint(lo)), "r"(__float_as_uint(hi))); return r;
}
__device__ __forceinline__ float plo(ull x) { return __uint_as_float((uint)x); }
__device__ __forceinline__ float phi(ull x) { return __uint_as_float((uint)(x >> 32)); }

__device__ __forceinline__ ull shflx64(ull x, int m) {
    uint lo = (uint)x, hi = (uint)(x >> 32);
    lo = __shfl_xor_sync(FULLM, lo, m);
    hi = __shfl_xor_sync(FULLM, hi, m);
    return (ull)lo | ((ull)hi << 32);
}

__global__ __launch_bounds__(WARPS * 32)
void lfa_kernel(const float* __restrict__ features,
                const float* __restrict__ geom,
                const float* __restrict__ w,
                const float* __restrict__ bias,
                const long long* __restrict__ nidx,
                float* __restrict__ out,
                int npts)
{
    __shared__ alignas(16) float4 sg[WARPS][KK];   // raw geom per warp

    const int lane = threadIdx.x & 31;
    const int wid  = threadIdx.x >> 5;
    const int p    = lane & 15;        // sub-lane within half
    const int half = lane >> 4;        // 0: k 0-7, 1: k 8-15

    // ---- per-warp index dtype detection ----
    // Probe first 16 values as int64: if data is really int32, an 8B read packs
    // two indices -> value >= 2^32 w.h.p. (false-64 prob ~ 16384^-16).
    long long probe = nidx[p];
    bool okp = (probe >= 0) && (probe < (long long)NN);
    unsigned bal = __ballot_sync(FULLM, okp);
    const bool is64 = ((bal & 0xFFFFu) == 0xFFFFu);

    // ---- per-warp weight/bias registers ----
    // lane owns d-pairs A=(p, p+32), B=(p+16, p+48)
    const float4* w4 = reinterpret_cast<const float4*>(w);
    float4 wa = w4[p],      wb = w4[p + 32];
    float4 wc = w4[p + 16], wd = w4[p + 48];
    const ull wA0 = pk2(wa.x, wb.x), wA1 = pk2(wa.y, wb.y);
    const ull wA2 = pk2(wa.z, wb.z), wA3 = pk2(wa.w, wb.w);
    const ull wB0 = pk2(wc.x, wd.x), wB1 = pk2(wc.y, wd.y);
    const ull wB2 = pk2(wc.z, wd.z), wB3 = pk2(wc.w, wd.w);
    const ull bA  = pk2(bias[p],      bias[p + 32]);
    const ull bB  = pk2(bias[p + 16], bias[p + 48]);

    const ull C1 = dup2((1.0f + SLOPE) * 0.5f / (float)KK);
    const ull C2 = dup2((1.0f - SLOPE) * 0.5f / (float)KK);
    const ull CM = dup2(1.0f / (float)KK);

    const int gwarp   = blockIdx.x * WARPS + wid;
    const int nwtotal = gridDim.x * WARPS;

    for (int pt = gwarp; pt < npts; pt += nwtotal) {
        const int bb = pt / NN;

        // ---- stage: geom + idx (lanes 0-15), geom into smem ----
        int idxv = 0;
        if (lane < KK) {
            float4 g = reinterpret_cast<const float4*>(geom)[(size_t)pt * KK + lane];
            sg[wid][lane] = g;
            long long v;
            if (is64) v = nidx[(size_t)pt * KK + lane];
            else      v = (long long)reinterpret_cast<const int*>(nidx)[(size_t)pt * KK + lane];
            idxv = (int)v;
        }
        __syncwarp();

        // ---- gather: half-split, 8 x LDG.128 (lane owns channels 4p..4p+3) ----
        const float* fb = features + (size_t)bb * NN * CC + 4 * p;
        ulonglong2 v0, v1, v2, v3, v4, v5, v6, v7;
        {
            int r0 = __shfl_sync(FULLM, idxv, 0 + 8 * half);
            int r1 = __shfl_sync(FULLM, idxv, 1 + 8 * half);
            int r2 = __shfl_sync(FULLM, idxv, 2 + 8 * half);
            int r3 = __shfl_sync(FULLM, idxv, 3 + 8 * half);
            int r4 = __shfl_sync(FULLM, idxv, 4 + 8 * half);
            int r5 = __shfl_sync(FULLM, idxv, 5 + 8 * half);
            int r6 = __shfl_sync(FULLM, idxv, 6 + 8 * half);
            int r7 = __shfl_sync(FULLM, idxv, 7 + 8 * half);
            v0 = *reinterpret_cast<const ulonglong2*>(fb + (size_t)r0 * CC);
            v1 = *reinterpret_cast<const ulonglong2*>(fb + (size_t)r1 * CC);
            v2 = *reinterpret_cast<const ulonglong2*>(fb + (size_t)r2 * CC);
            v3 = *reinterpret_cast<const ulonglong2*>(fb + (size_t)r3 * CC);
            v4 = *reinterpret_cast<const ulonglong2*>(fb + (size_t)r4 * CC);
            v5 = *reinterpret_cast<const ulonglong2*>(fb + (size_t)r5 * CC);
            v6 = *reinterpret_cast<const ulonglong2*>(fb + (size_t)r6 * CC);
            v7 = *reinterpret_cast<const ulonglong2*>(fb + (size_t)r7 * CC);
        }

        // ---- geom MLP while gather loads are in flight ----
        ull sA = 0ULL, aA = 0ULL, sB = 0ULL, aB = 0ULL;
#pragma unroll
        for (int i = 0; i < 8; i++) {
            float4 gk = sg[wid][i + 8 * half];     // LDS.128, 2 broadcast addrs
            ull g0 = dup2(gk.x), g1 = dup2(gk.y), g2 = dup2(gk.z), g3 = dup2(gk.w);
            ull xA = pfma(g3, wA3, pfma(g2, wA2, pfma(g1, wA1, pfma(g0, wA0, bA))));
            ull xB = pfma(g3, wB3, pfma(g2, wB2, pfma(g1, wB1, pfma(g0, wB0, bB))));
            sA = padd(sA, xA);  aA = padd(aA, xA & ABSM);
            sB = padd(sB, xB);  aB = padd(aB, xB & ABSM);
        }
        // combine k-halves (partner lane l^16 has same d-pairs, other k-half)
        sA = padd(sA, shflx64(sA, 16));
        aA = padd(aA, shflx64(aA, 16));
        sB = padd(sB, shflx64(sB, 16));
        aB = padd(aB, shflx64(aB, 16));

        // mean_k lrelu(x) = c1*sum(x) + c2*sum(|x|)   (slope 0.1)
        const ull tA = pfma(sA, C1, pmul(aA, C2));
        const ull tB = pfma(sB, C1, pmul(aB, C2));

        // ---- gather mean: tree-sum 8 rows, then k-half butterfly ----
        ull ac0 = padd(padd(v0.x, v1.x), padd(v2.x, v3.x));
        ull ac1 = padd(padd(v0.y, v1.y), padd(v2.y, v3.y));
        ac0 = padd(ac0, padd(padd(v4.x, v5.x), padd(v6.x, v7.x)));
        ac1 = padd(ac1, padd(padd(v4.y, v5.y), padd(v6.y, v7.y)));
        ac0 = padd(ac0, shflx64(ac0, 16));
        ac1 = padd(ac1, shflx64(ac1, 16));
        ac0 = pmul(ac0, CM);
        ac1 = pmul(ac1, CM);

        // ---- stores ----
        float* op = out + (size_t)pt * (DD + CC);
        const ull tv = half ? tB : tA;     // lane -> d=lane and d=lane+32
        op[lane]      = plo(tv);
        op[lane + 32] = phi(tv);
        *reinterpret_cast<ull*>(op + DD + 4 * p + 2 * half) = half ? ac1 : ac0;
    }
}

extern "C" void kernel_launch(void* const* d_in, const int* in_sizes, int n_in,
                              void* d_out, int out_size)
{
    const float*     features = (const float*)d_in[0];
    const float*     geom     = (const float*)d_in[1];
    const float*     w        = (const float*)d_in[2];
    const float*     b        = (const float*)d_in[3];
    const long long* nidx     = (const long long*)d_in[4];

    const int npts = in_sizes[1] / (KK * 4);             // B*N from geom
    int blocks = (npts + WARPS * PPW - 1) / (WARPS * PPW);
    if (blocks < 1) blocks = 1;

    lfa_kernel<<<blocks, WARPS * 32>>>(features, geom, w, b, nidx, (float*)d_out, npts);
}